// round 13
// baseline (speedup 1.0000x reference)
#include <cuda_runtime.h>

// Problem constants
#define IN_DIM  8192
#define OUT_DIM 8192

// Tiling: 128 threads x float2 = 256 cols/stripe, 128 row chunks
#define P_THREADS 128
#define VEC 2
#define COLS_PER_BLOCK (P_THREADS * VEC)            // 256
#define N_STRIPES      (OUT_DIM / COLS_PER_BLOCK)   // 32
#define N_ROW_CHUNKS   128
#define ROWS_PER_CHUNK (IN_DIM / N_ROW_CHUNKS)      // 64

// Zero-initialized accumulators: [0:OUT_DIM) = bound_l sums, [OUT_DIM:2*OUT_DIM) = bound_u.
// Invariant: zeroed at the end of every launch by the electing blocks, so each
// graph replay starts from zero.
__device__ float g_acc[2 * OUT_DIM];
__device__ unsigned int g_count[N_STRIPES];

__device__ __forceinline__ void red_add_v2(float* p, float x, float y) {
    asm volatile("red.global.add.v2.f32 [%0], {%1, %2};"
                 :: "l"(p), "f"(x), "f"(y) : "memory");
}

__global__ __launch_bounds__(P_THREADS)
void ibp_fused_kernel(const float* __restrict__ l,
                      const float* __restrict__ u,
                      const float* __restrict__ w,
                      const float* __restrict__ bias,
                      float* __restrict__ out) {
    __shared__ float sc[ROWS_PER_CHUNK];
    __shared__ float sr[ROWS_PER_CHUNK];
    __shared__ unsigned int s_is_last;

    const int stripe = blockIdx.x;
    const int chunk  = blockIdx.y;
    const int col0 = stripe * COLS_PER_BLOCK + threadIdx.x * VEC;
    const int row0 = chunk * ROWS_PER_CHUNK;

    if (threadIdx.x < ROWS_PER_CHUNK) {
        int i = threadIdx.x;
        float lv = l[row0 + i];
        float uv = u[row0 + i];
        sc[i] = 0.5f * (lv + uv);
        sr[i] = 0.5f * (uv - lv);
    }
    __syncthreads();

    float s1x = 0.f, s1y = 0.f;
    float s2x = 0.f, s2y = 0.f;

    const float2* __restrict__ wp =
        reinterpret_cast<const float2*>(w + (size_t)row0 * OUT_DIM + col0);
    const size_t rstride = OUT_DIM / 2;

    #pragma unroll 16
    for (int i = 0; i < ROWS_PER_CHUNK; i++) {
        float2 wv = __ldcs(&wp[(size_t)i * rstride]);   // stream, evict-first
        float c = sc[i];
        float r = sr[i];
        s1x = fmaf(c, wv.x, s1x);
        s1y = fmaf(c, wv.y, s1y);
        s2x = fmaf(r, fabsf(wv.x), s2x);
        s2y = fmaf(r, fabsf(wv.y), s2y);
    }

    // Accumulate into the zero-initialized L2-resident accumulators.
    red_add_v2(g_acc + col0,           s1x - s2x, s1y - s2y);   // bound_l sum
    red_add_v2(g_acc + OUT_DIM + col0, s1x + s2x, s1y + s2y);   // bound_u sum

    // Publish: every thread fences its own REDs, THEN barrier so all 128
    // threads' REDs are globally visible before thread 0 takes the ticket.
    __threadfence();
    __syncthreads();
    if (threadIdx.x == 0) {
        unsigned int old = atomicAdd(&g_count[stripe], 1u);
        s_is_last = (old == N_ROW_CHUNKS - 1) ? 1u : 0u;
    }
    __syncthreads();
    if (!s_is_last) return;

    // ---- Elected (last) block of this stripe: finalize 256 columns ----
    __threadfence();   // acquire: all other blocks' REDs to our columns visible
    const int c0 = stripe * COLS_PER_BLOCK + threadIdx.x * VEC;
    float2 vl = __ldcg(reinterpret_cast<const float2*>(g_acc + c0));
    float2 vu = __ldcg(reinterpret_cast<const float2*>(g_acc + OUT_DIM + c0));
    float2 b  = *reinterpret_cast<const float2*>(bias + c0);
    float2 lo = make_float2(vl.x + b.x, vl.y + b.y);
    float2 hi = make_float2(vu.x + b.x, vu.y + b.y);
    *reinterpret_cast<float2*>(out + c0)           = lo;   // bound_l
    *reinterpret_cast<float2*>(out + OUT_DIM + c0) = hi;   // bound_u

    // Reset accumulators + counter for the next launch / graph replay.
    const float2 z = make_float2(0.f, 0.f);
    *reinterpret_cast<float2*>(g_acc + c0)           = z;
    *reinterpret_cast<float2*>(g_acc + OUT_DIM + c0) = z;
    if (threadIdx.x == 0) g_count[stripe] = 0u;
}

extern "C" void kernel_launch(void* const* d_in, const int* in_sizes, int n_in,
                              void* d_out, int out_size) {
    const float* l    = (const float*)d_in[0];
    const float* u    = (const float*)d_in[1];
    const float* w    = (const float*)d_in[2];
    const float* bias = (const float*)d_in[3];
    float* out = (float*)d_out;

    dim3 grid(N_STRIPES, N_ROW_CHUNKS);   // (32, 128) = 4096 CTAs, one launch
    ibp_fused_kernel<<<grid, P_THREADS>>>(l, u, w, bias, out);
}

// round 14
// speedup vs baseline: 1.0529x; 1.0529x over previous
#include <cuda_runtime.h>

// Problem constants
#define IN_DIM  8192
#define OUT_DIM 8192

// Partial-kernel tiling: 128 threads x float2 = 256 cols/block, 128 row chunks
#define P_THREADS 128
#define VEC 2
#define COLS_PER_BLOCK (P_THREADS * VEC)            // 256
#define N_STRIPES      (OUT_DIM / COLS_PER_BLOCK)   // 32
#define N_ROW_CHUNKS   128
#define ROWS_PER_CHUNK (IN_DIM / N_ROW_CHUNKS)      // 64

// Init: seed both output halves with bias (out is poisoned each replay)
#define I_THREADS 256
__global__ __launch_bounds__(I_THREADS)
void ibp_init_kernel(const float* __restrict__ bias,
                     float* __restrict__ out) {
    const int i = blockIdx.x * I_THREADS + threadIdx.x;   // [0, 2048) float4s
    float4 b = reinterpret_cast<const float4*>(bias)[i];
    reinterpret_cast<float4*>(out)[i] = b;                // bound_l base
    reinterpret_cast<float4*>(out + OUT_DIM)[i] = b;      // bound_u base
#if __CUDA_ARCH__ >= 900
    // Let the dependent (partial) kernel begin launching immediately; its
    // cudaGridDependencySynchronize() still waits for our stores to be visible.
    cudaTriggerProgrammaticLaunchCompletion();
#endif
}

__device__ __forceinline__ void red_add_v2(float* p, float x, float y) {
    asm volatile("red.global.add.v2.f32 [%0], {%1, %2};"
                 :: "l"(p), "f"(x), "f"(y) : "memory");
}

__global__ __launch_bounds__(P_THREADS)
void ibp_partial_kernel(const float* __restrict__ l,
                        const float* __restrict__ u,
                        const float* __restrict__ w,
                        float* __restrict__ out) {
    __shared__ float sc[ROWS_PER_CHUNK];
    __shared__ float sr[ROWS_PER_CHUNK];

    const int col0 = blockIdx.x * COLS_PER_BLOCK + threadIdx.x * VEC;
    const int row0 = blockIdx.y * ROWS_PER_CHUNK;

    if (threadIdx.x < ROWS_PER_CHUNK) {
        int i = threadIdx.x;
        float lv = l[row0 + i];
        float uv = u[row0 + i];
        sc[i] = 0.5f * (lv + uv);
        sr[i] = 0.5f * (uv - lv);
    }
    __syncthreads();

    float s1x = 0.f, s1y = 0.f;
    float s2x = 0.f, s2y = 0.f;

    const float2* __restrict__ wp =
        reinterpret_cast<const float2*>(w + (size_t)row0 * OUT_DIM + col0);
    const size_t rstride = OUT_DIM / 2;

    #pragma unroll 16
    for (int i = 0; i < ROWS_PER_CHUNK; i++) {
        float2 wv = __ldcs(&wp[(size_t)i * rstride]);   // stream, evict-first
        float c = sc[i];
        float r = sr[i];
        s1x = fmaf(c, wv.x, s1x);
        s1y = fmaf(c, wv.y, s1y);
        s2x = fmaf(r, fabsf(wv.x), s2x);
        s2y = fmaf(r, fabsf(wv.y), s2y);
    }

#if __CUDA_ARCH__ >= 900
    // PDL: wait until the init kernel's bias-seeding stores are visible
    // before accumulating into out. By now the ~40us mainloop has long
    // outlived the sub-microsecond init, so this wait is free.
    cudaGridDependencySynchronize();
#endif

    // Accumulate directly into the (bias-seeded, L2-resident) outputs.
    red_add_v2(out + col0,           s1x - s2x, s1y - s2y);   // bound_l
    red_add_v2(out + OUT_DIM + col0, s1x + s2x, s1y + s2y);   // bound_u
}

extern "C" void kernel_launch(void* const* d_in, const int* in_sizes, int n_in,
                              void* d_out, int out_size) {
    const float* l    = (const float*)d_in[0];
    const float* u    = (const float*)d_in[1];
    const float* w    = (const float*)d_in[2];
    const float* bias = (const float*)d_in[3];
    float* out = (float*)d_out;

    // Primary: bias seeding (8 CTAs)
    ibp_init_kernel<<<(OUT_DIM / 4) / I_THREADS, I_THREADS>>>(bias, out);

    // Secondary: main stream, launched with programmatic stream serialization
    // so it overlaps with the init launch; it synchronizes on init's memory
    // via cudaGridDependencySynchronize() just before its REDs.
    cudaLaunchConfig_t cfg = {};
    cfg.gridDim  = dim3(N_STRIPES, N_ROW_CHUNKS);   // (32, 128) = 4096 CTAs
    cfg.blockDim = dim3(P_THREADS);
    cfg.dynamicSmemBytes = 0;
    cfg.stream = 0;
    cudaLaunchAttribute attrs[1];
    attrs[0].id = cudaLaunchAttributeProgrammaticStreamSerialization;
    attrs[0].val.programmaticStreamSerializationAllowed = 1;
    cfg.attrs = attrs;
    cfg.numAttrs = 1;
    cudaLaunchKernelEx(&cfg, ibp_partial_kernel, l, u, w, out);
}

// round 15
// speedup vs baseline: 1.0537x; 1.0007x over previous
#include <cuda_runtime.h>

// Problem constants
#define IN_DIM  8192
#define OUT_DIM 8192

// Partial-kernel tiling: 128 threads x float2 = 256 cols/block, 128 row chunks
#define P_THREADS 128
#define VEC 2
#define COLS_PER_BLOCK (P_THREADS * VEC)            // 256
#define N_STRIPES      (OUT_DIM / COLS_PER_BLOCK)   // 32
#define N_ROW_CHUNKS   128
#define ROWS_PER_CHUNK (IN_DIM / N_ROW_CHUNKS)      // 64

// Init: seed both output halves with bias (out is poisoned each replay)
#define I_THREADS 256
__global__ __launch_bounds__(I_THREADS)
void ibp_init_kernel(const float* __restrict__ bias,
                     float* __restrict__ out) {
    const int i = blockIdx.x * I_THREADS + threadIdx.x;   // [0, 2048) float4s
    float4 b = reinterpret_cast<const float4*>(bias)[i];
    reinterpret_cast<float4*>(out)[i] = b;                // bound_l base
    reinterpret_cast<float4*>(out + OUT_DIM)[i] = b;      // bound_u base
#if __CUDA_ARCH__ >= 900
    cudaTriggerProgrammaticLaunchCompletion();
#endif
}

__device__ __forceinline__ void red_add_v2(float* p, float x, float y) {
    asm volatile("red.global.add.v2.f32 [%0], {%1, %2};"
                 :: "l"(p), "f"(x), "f"(y) : "memory");
}

__global__ __launch_bounds__(P_THREADS)
void ibp_partial_kernel(const float* __restrict__ l,
                        const float* __restrict__ u,
                        const float* __restrict__ w,
                        float* __restrict__ out) {
    __shared__ float sc[ROWS_PER_CHUNK];
    __shared__ float sr[ROWS_PER_CHUNK];

    const int col0 = blockIdx.x * COLS_PER_BLOCK + threadIdx.x * VEC;
    const int row0 = blockIdx.y * ROWS_PER_CHUNK;

    if (threadIdx.x < ROWS_PER_CHUNK) {
        int i = threadIdx.x;
        float lv = l[row0 + i];
        float uv = u[row0 + i];
        sc[i] = 0.5f * (lv + uv);
        sr[i] = 0.5f * (uv - lv);
    }

#if __CUDA_ARCH__ >= 900
    // PDL: wait for the init kernel's bias-seeding stores BEFORE the mainloop.
    // Only the earliest blocks (overlapping the <1us init) ever actually wait;
    // the epilogue below stays a clean load->FMA->RED stream.
    cudaGridDependencySynchronize();
#endif
    __syncthreads();

    float s1x = 0.f, s1y = 0.f;
    float s2x = 0.f, s2y = 0.f;

    const float2* __restrict__ wp =
        reinterpret_cast<const float2*>(w + (size_t)row0 * OUT_DIM + col0);
    const size_t rstride = OUT_DIM / 2;

    #pragma unroll 16
    for (int i = 0; i < ROWS_PER_CHUNK; i++) {
        float2 wv = __ldcs(&wp[(size_t)i * rstride]);   // stream, evict-first
        float c = sc[i];
        float r = sr[i];
        s1x = fmaf(c, wv.x, s1x);
        s1y = fmaf(c, wv.y, s1y);
        s2x = fmaf(r, fabsf(wv.x), s2x);
        s2y = fmaf(r, fabsf(wv.y), s2y);
    }

    // Accumulate directly into the (bias-seeded, L2-resident) outputs.
    red_add_v2(out + col0,           s1x - s2x, s1y - s2y);   // bound_l
    red_add_v2(out + OUT_DIM + col0, s1x + s2x, s1y + s2y);   // bound_u
}

extern "C" void kernel_launch(void* const* d_in, const int* in_sizes, int n_in,
                              void* d_out, int out_size) {
    const float* l    = (const float*)d_in[0];
    const float* u    = (const float*)d_in[1];
    const float* w    = (const float*)d_in[2];
    const float* bias = (const float*)d_in[3];
    float* out = (float*)d_out;

    // Primary: bias seeding (8 CTAs)
    ibp_init_kernel<<<(OUT_DIM / 4) / I_THREADS, I_THREADS>>>(bias, out);

    // Secondary: main stream with programmatic stream serialization so its
    // launch overlaps the init kernel.
    cudaLaunchConfig_t cfg = {};
    cfg.gridDim  = dim3(N_STRIPES, N_ROW_CHUNKS);   // (32, 128) = 4096 CTAs
    cfg.blockDim = dim3(P_THREADS);
    cfg.dynamicSmemBytes = 0;
    cfg.stream = 0;
    cudaLaunchAttribute attrs[1];
    attrs[0].id = cudaLaunchAttributeProgrammaticStreamSerialization;
    attrs[0].val.programmaticStreamSerializationAllowed = 1;
    cfg.attrs = attrs;
    cfg.numAttrs = 1;
    cudaLaunchKernelEx(&cfg, ibp_partial_kernel, l, u, w, out);
}